// round 1
// baseline (speedup 1.0000x reference)
#include <cuda_runtime.h>
#include <cuda_bf16.h>
#include <math.h>

#define BB 2
#define LIMG 2048
#define LTXT 512
#define DMODEL 2048
#define NH 16
#define DHD 128
#define LKTOT (LTXT + LIMG)   // 2560
#define EPSV 1e-6f

// ---------------- scratch (device globals; no allocations allowed) ----------
__device__ float g_qkv_raw[BB * LIMG * 3 * DMODEL];        // 25.2M
__device__ float g_kv_raw[BB * LTXT * 2 * DMODEL];         // 4.2M
__device__ float g_qbuf[BB * NH * LIMG * DHD];             // 8.4M
__device__ float g_kbuf[BB * NH * LKTOT * DHD];            // 10.5M
__device__ float g_vbuf[BB * NH * LKTOT * DHD];            // 10.5M
__device__ float g_scores[BB * NH * LIMG * LKTOT];         // 167.8M (671MB)
__device__ float g_attn_raw[BB * NH * LIMG * DHD];         // 8.4M
__device__ float g_attn2[BB * LIMG * NH * DHD];            // 8.4M
__device__ int   g_len[BB];

// ---------------- generic tiled fp32 GEMM: C = A @ B (or A @ B^T) -----------
// 128x128 block tile, BK=8, 256 threads, 8x8 micro-tile per thread.
// Batched via blockIdx.z with element strides sA,sB,sC.
template <bool TRB>
__global__ void __launch_bounds__(256) gemm_tile(
    const float* __restrict__ A, const float* __restrict__ B,
    float* __restrict__ C, int M, int N, int K,
    long sA, long sB, long sC)
{
    __shared__ float As[8][128];
    __shared__ float Bs[8][128];

    A += (long)blockIdx.z * sA;
    B += (long)blockIdx.z * sB;
    C += (long)blockIdx.z * sC;

    const int m0 = blockIdx.y * 128;
    const int n0 = blockIdx.x * 128;
    const int t  = threadIdx.x;
    const int tx = t & 15;
    const int ty = t >> 4;

    // A tile load map (also used for B in TRB mode): 128 rows x 8 cols
    const int ar = t >> 1;
    const int ac = (t & 1) * 4;
    // B tile load map (NN): 8 rows x 128 cols
    const int br = t >> 5;
    const int bc = (t & 31) * 4;

    float acc[8][8];
#pragma unroll
    for (int i = 0; i < 8; i++)
#pragma unroll
        for (int j = 0; j < 8; j++) acc[i][j] = 0.f;

    for (int k0 = 0; k0 < K; k0 += 8) {
        float4 av = *(const float4*)&A[(long)(m0 + ar) * K + k0 + ac];
        As[ac + 0][ar] = av.x;
        As[ac + 1][ar] = av.y;
        As[ac + 2][ar] = av.z;
        As[ac + 3][ar] = av.w;
        if (TRB) {
            float4 bv = *(const float4*)&B[(long)(n0 + ar) * K + k0 + ac];
            Bs[ac + 0][ar] = bv.x;
            Bs[ac + 1][ar] = bv.y;
            Bs[ac + 2][ar] = bv.z;
            Bs[ac + 3][ar] = bv.w;
        } else {
            float4 bv = *(const float4*)&B[(long)(k0 + br) * N + n0 + bc];
            *(float4*)&Bs[br][bc] = bv;
        }
        __syncthreads();
#pragma unroll
        for (int k = 0; k < 8; k++) {
            float4 a0 = *(const float4*)&As[k][ty * 8];
            float4 a1 = *(const float4*)&As[k][ty * 8 + 4];
            float4 b0 = *(const float4*)&Bs[k][tx * 8];
            float4 b1 = *(const float4*)&Bs[k][tx * 8 + 4];
            float ra[8] = {a0.x, a0.y, a0.z, a0.w, a1.x, a1.y, a1.z, a1.w};
            float rb[8] = {b0.x, b0.y, b0.z, b0.w, b1.x, b1.y, b1.z, b1.w};
#pragma unroll
            for (int i = 0; i < 8; i++)
#pragma unroll
                for (int j = 0; j < 8; j++) acc[i][j] += ra[i] * rb[j];
        }
        __syncthreads();
    }

#pragma unroll
    for (int i = 0; i < 8; i++) {
        float* cp = &C[(long)(m0 + ty * 8 + i) * N + n0 + tx * 8];
        *(float4*)cp       = make_float4(acc[i][0], acc[i][1], acc[i][2], acc[i][3]);
        *(float4*)(cp + 4) = make_float4(acc[i][4], acc[i][5], acc[i][6], acc[i][7]);
    }
}

// ---------------- image QKV transform: RMSNorm + RoPE + layout --------------
// one warp per (b,l,h) row; lane owns 4 consecutive d (one float4 = 2 rope pairs)
__global__ void __launch_bounds__(256) transform_img(
    const float* __restrict__ rope, const float* __restrict__ gq,
    const float* __restrict__ gk)
{
    int r    = blockIdx.x * 8 + (threadIdx.x >> 5);     // over B*LIMG*NH
    int lane = threadIdx.x & 31;
    int h  = r & (NH - 1);
    int bl = r >> 4;                 // b*LIMG + l
    int l  = bl & (LIMG - 1);
    int b  = bl >> 11;
    int d  = lane * 4;

    const float* row = g_qkv_raw + (long)bl * (3 * DMODEL) + h * DHD;
    float4 q = *(const float4*)&row[d];
    float4 k = *(const float4*)&row[DMODEL + d];
    float4 v = *(const float4*)&row[2 * DMODEL + d];

    float sq = q.x * q.x + q.y * q.y + q.z * q.z + q.w * q.w;
    float sk = k.x * k.x + k.y * k.y + k.z * k.z + k.w * k.w;
#pragma unroll
    for (int o = 16; o; o >>= 1) {
        sq += __shfl_xor_sync(0xffffffffu, sq, o);
        sk += __shfl_xor_sync(0xffffffffu, sk, o);
    }
    float rq = rsqrtf(sq * (1.f / DHD) + EPSV);
    float rk = rsqrtf(sk * (1.f / DHD) + EPSV);

    float4 wq = *(const float4*)&gq[d];
    float4 wk = *(const float4*)&gk[d];
    q.x *= rq * wq.x; q.y *= rq * wq.y; q.z *= rq * wq.z; q.w *= rq * wq.w;
    k.x *= rk * wk.x; k.y *= rk * wk.y; k.z *= rk * wk.z; k.w *= rk * wk.w;

    // rope table: [b][l][pair][2][2], pair = lane*2 and lane*2+1
    const float* fc = rope + (((long)bl) * 64 + lane * 2) * 4;
    float4 f0 = *(const float4*)fc;         // {cos, -sin, sin, cos}
    float4 f1 = *(const float4*)(fc + 4);

    float4 qo, ko;
    qo.x = f0.x * q.x + f0.y * q.y;  qo.y = f0.z * q.x + f0.w * q.y;
    qo.z = f1.x * q.z + f1.y * q.w;  qo.w = f1.z * q.z + f1.w * q.w;
    ko.x = f0.x * k.x + f0.y * k.y;  ko.y = f0.z * k.x + f0.w * k.y;
    ko.z = f1.x * k.z + f1.y * k.w;  ko.w = f1.z * k.z + f1.w * k.w;

    long qi = (((long)(b * NH + h)) * LIMG + l) * DHD + d;
    *(float4*)&g_qbuf[qi] = qo;
    long ki = (((long)(b * NH + h)) * LKTOT + (LTXT + l)) * DHD + d;
    *(float4*)&g_kbuf[ki] = ko;
    *(float4*)&g_vbuf[ki] = v;
}

// ---------------- text KV transform: RMSNorm(k) + layout --------------------
__global__ void __launch_bounds__(256) transform_txt(const float* __restrict__ gak)
{
    int r    = blockIdx.x * 8 + (threadIdx.x >> 5);     // over B*LTXT*NH
    int lane = threadIdx.x & 31;
    int h  = r & (NH - 1);
    int bl = r >> 4;                 // b*LTXT + l
    int l  = bl & (LTXT - 1);
    int b  = bl >> 9;
    int d  = lane * 4;

    const float* row = g_kv_raw + (long)bl * (2 * DMODEL) + h * DHD;
    float4 k = *(const float4*)&row[d];
    float4 v = *(const float4*)&row[DMODEL + d];

    float sk = k.x * k.x + k.y * k.y + k.z * k.z + k.w * k.w;
#pragma unroll
    for (int o = 16; o; o >>= 1) sk += __shfl_xor_sync(0xffffffffu, sk, o);
    float rk = rsqrtf(sk * (1.f / DHD) + EPSV);

    float4 wk = *(const float4*)&gak[d];
    k.x *= rk * wk.x; k.y *= rk * wk.y; k.z *= rk * wk.z; k.w *= rk * wk.w;

    long ki = (((long)(b * NH + h)) * LKTOT + l) * DHD + d;
    *(float4*)&g_kbuf[ki] = k;
    *(float4*)&g_vbuf[ki] = v;
}

// ---------------- mask lengths (dtype-agnostic: bool(1B) or int32) ----------
__global__ void lengths_kernel(const unsigned char* __restrict__ mask)
{
    __shared__ int red[256];
    int b = blockIdx.x;
    // byte[1]: if mask is 1-byte bool it's mask[0][1]=1 (len>=128); if int32 it's 0.
    int es = (mask[1] != 0) ? 1 : 4;
    int nbytes = LTXT * es;
    const unsigned char* p = mask + (long)b * nbytes;
    int c = 0;
    for (int i = threadIdx.x; i < nbytes; i += 256) c += (p[i] != 0);
    red[threadIdx.x] = c;
    __syncthreads();
    for (int o = 128; o; o >>= 1) {
        if (threadIdx.x < o) red[threadIdx.x] += red[threadIdx.x + o];
        __syncthreads();
    }
    if (threadIdx.x == 0) g_len[b] = red[0];
}

// ---------------- masked softmax over scores rows (in place) ----------------
__global__ void __launch_bounds__(256) softmax_kernel()
{
    const float scale = 0.08838834764831845f;   // 1/sqrt(128)
    long row = blockIdx.x;                       // B*NH*LIMG = 65536
    int b = (int)(row >> 15);
    float* p = g_scores + row * (long)LKTOT;
    int len = g_len[b];
    int t = threadIdx.x;

    float vals[10];
    float m = -INFINITY;
#pragma unroll
    for (int j = 0; j < 10; j++) {
        int i = t + j * 256;
        float x = p[i] * scale;
        bool valid = (i >= LTXT) || (i < len);
        x = valid ? x : -INFINITY;
        vals[j] = x;
        m = fmaxf(m, x);
    }
    __shared__ float red[256];
    red[t] = m; __syncthreads();
    for (int o = 128; o; o >>= 1) {
        if (t < o) red[t] = fmaxf(red[t], red[t + o]);
        __syncthreads();
    }
    m = red[0]; __syncthreads();

    float s = 0.f;
#pragma unroll
    for (int j = 0; j < 10; j++) {
        float e = __expf(vals[j] - m);
        vals[j] = e;
        s += e;
    }
    red[t] = s; __syncthreads();
    for (int o = 128; o; o >>= 1) {
        if (t < o) red[t] += red[t + o];
        __syncthreads();
    }
    float inv = 1.f / red[0];
#pragma unroll
    for (int j = 0; j < 10; j++) p[t + j * 256] = vals[j] * inv;
}

// ---------------- [B,H,L,DH] -> [B,L,H*DH] repack ---------------------------
__global__ void __launch_bounds__(128) repack_kernel()
{
    int r = blockIdx.x;               // over B*NH*LIMG
    int t = threadIdx.x;              // 128
    int b = r >> 15;
    int h = (r >> 11) & (NH - 1);
    int l = r & (LIMG - 1);
    long oi = (((long)(b * LIMG + l)) * NH + h) * DHD + t;
    g_attn2[oi] = g_attn_raw[(long)r * DHD + t];
}

// ---------------- launch ----------------------------------------------------
extern "C" void kernel_launch(void* const* d_in, const int* in_sizes, int n_in,
                              void* d_out, int out_size)
{
    const float* hidden = (const float*)d_in[0];
    const float* enc    = (const float*)d_in[1];
    const unsigned char* mask = (const unsigned char*)d_in[2];
    const float* rope   = (const float*)d_in[3];
    const float* w_qkv  = (const float*)d_in[4];
    const float* w_kv   = (const float*)d_in[5];
    const float* w_o    = (const float*)d_in[6];
    const float* gq     = (const float*)d_in[7];
    const float* gk     = (const float*)d_in[8];
    const float* gak    = (const float*)d_in[9];
    float* out = (float*)d_out;

    float *qkv_raw, *kv_raw, *qbuf, *kbuf, *vbuf, *scores, *attn_raw, *attn2;
    cudaGetSymbolAddress((void**)&qkv_raw,  g_qkv_raw);
    cudaGetSymbolAddress((void**)&kv_raw,   g_kv_raw);
    cudaGetSymbolAddress((void**)&qbuf,     g_qbuf);
    cudaGetSymbolAddress((void**)&kbuf,     g_kbuf);
    cudaGetSymbolAddress((void**)&vbuf,     g_vbuf);
    cudaGetSymbolAddress((void**)&scores,   g_scores);
    cudaGetSymbolAddress((void**)&attn_raw, g_attn_raw);
    cudaGetSymbolAddress((void**)&attn2,    g_attn2);

    dim3 blk(256);

    // 1) image QKV projection: [4096,2048]@[2048,6144]
    gemm_tile<false><<<dim3(6144 / 128, 4096 / 128, 1), blk>>>(
        hidden, w_qkv, qkv_raw, 4096, 6144, 2048, 0, 0, 0);
    // 2) text KV projection: [1024,2048]@[2048,4096]
    gemm_tile<false><<<dim3(4096 / 128, 1024 / 128, 1), blk>>>(
        enc, w_kv, kv_raw, 1024, 4096, 2048, 0, 0, 0);
    // 3) transforms
    transform_img<<<BB * LIMG * NH / 8, blk>>>(rope, gq, gk);
    transform_txt<<<BB * LTXT * NH / 8, blk>>>(gak);
    lengths_kernel<<<BB, blk>>>(mask);
    // 4) scores = Q @ K^T, batched over 32 (b,h)
    gemm_tile<true><<<dim3(LKTOT / 128, LIMG / 128, BB * NH), blk>>>(
        qbuf, kbuf, scores, LIMG, LKTOT, DHD,
        (long)LIMG * DHD, (long)LKTOT * DHD, (long)LIMG * LKTOT);
    // 5) masked softmax
    softmax_kernel<<<BB * NH * LIMG, blk>>>();
    // 6) attn = P @ V, batched
    gemm_tile<false><<<dim3(1, LIMG / 128, BB * NH), blk>>>(
        scores, vbuf, attn_raw, LIMG, DHD, LKTOT,
        (long)LIMG * LKTOT, (long)LKTOT * DHD, (long)LIMG * DHD);
    // 7) repack to [B, L, H*DH]
    repack_kernel<<<BB * NH * LIMG, 128>>>();
    // 8) output projection: [4096,2048]@[2048,2048]
    gemm_tile<false><<<dim3(2048 / 128, 4096 / 128, 1), blk>>>(
        attn2, w_o, out, 4096, 2048, 2048, 0, 0, 0);
}

// round 2
// speedup vs baseline: 2.0151x; 2.0151x over previous
#include <cuda_runtime.h>
#include <cuda_bf16.h>
#include <math.h>

#define BB 2
#define LIMG 2048
#define LTXT 512
#define DMODEL 2048
#define NH 16
#define DHD 128
#define LKTOT (LTXT + LIMG)   // 2560
#define EPSV 1e-6f
#define SCALE 0.08838834764831845f  // 1/sqrt(128)

// ---------------- scratch (device globals; no allocations allowed) ----------
__device__ float g_qkv_raw[BB * LIMG * 3 * DMODEL];
__device__ float g_kv_raw[BB * LTXT * 2 * DMODEL];
__device__ float g_qbuf[BB * NH * LIMG * DHD];
__device__ float g_kbuf[BB * NH * LKTOT * DHD];
__device__ float g_vbuf[BB * NH * LKTOT * DHD];
__device__ float g_scores[BB * NH * LIMG * LKTOT];
__device__ float g_attn_raw[BB * NH * LIMG * DHD];
__device__ float g_attn2[BB * LIMG * NH * DHD];
__device__ int   g_len[BB];

__device__ __forceinline__ unsigned f2tf(float x) {
    unsigned u;
    asm("cvt.rna.tf32.f32 %0, %1;" : "=r"(u) : "f"(x));
    return u;
}

// ---------------- TF32 tensor-core GEMM: C = A @ B (or A @ B^T) -------------
// block tile 128x128, BK=32, 256 threads (8 warps, 4x2), warp tile 32x64.
// A,B staged in smem as [row][k] stride 36 (conflict-free 4*row+k bank map).
// mma.sync.m16n8k8 tf32, explicit cvt.rna at stage time.
template <bool TRB>
__global__ void __launch_bounds__(256) gemm_tf32(
    const float* __restrict__ A, const float* __restrict__ B,
    float* __restrict__ C, int M, int N, int K,
    long sA, long sB, long sC)
{
    __shared__ unsigned As[128 * 36];
    __shared__ unsigned Bs[128 * 36];

    A += (long)blockIdx.z * sA;
    B += (long)blockIdx.z * sB;
    C += (long)blockIdx.z * sC;

    const int t    = threadIdx.x;
    const int lane = t & 31;
    const int warp = t >> 5;
    const int wm   = (warp >> 1) * 32;
    const int wn   = (warp & 1) * 64;
    const int m0   = blockIdx.y * 128;
    const int n0   = blockIdx.x * 128;

    // row-major (k-contiguous) load map: row = t>>1, k base = (t&1)*16, 4 x float4
    const int lar = t >> 1;
    const int lak = (t & 1) * 16;
    // NN B load map: k = t>>3, n base = (t&7)*16, 4 x float4 along n
    const int lbk = t >> 3;
    const int lbn = (t & 7) * 16;

    float acc[2][8][4];
#pragma unroll
    for (int i = 0; i < 2; i++)
#pragma unroll
        for (int j = 0; j < 8; j++)
#pragma unroll
            for (int c = 0; c < 4; c++) acc[i][j][c] = 0.f;

    const float* Ap = A + (long)(m0 + lar) * K + lak;
    const float* Bp = TRB ? (B + (long)(n0 + lar) * K + lak)
                          : (B + (long)lbk * N + n0 + lbn);

    float4 pa[4], pb[4];
#pragma unroll
    for (int j = 0; j < 4; j++) {
        pa[j] = *(const float4*)(Ap + 4 * j);
        pb[j] = *(const float4*)(Bp + 4 * j);
    }

    for (int k0 = 0; k0 < K; k0 += 32) {
        // stage current tiles into smem (cvt to tf32)
#pragma unroll
        for (int j = 0; j < 4; j++) {
            unsigned* d = &As[lar * 36 + lak + 4 * j];
            d[0] = f2tf(pa[j].x); d[1] = f2tf(pa[j].y);
            d[2] = f2tf(pa[j].z); d[3] = f2tf(pa[j].w);
        }
        if (TRB) {
#pragma unroll
            for (int j = 0; j < 4; j++) {
                unsigned* d = &Bs[lar * 36 + lak + 4 * j];
                d[0] = f2tf(pb[j].x); d[1] = f2tf(pb[j].y);
                d[2] = f2tf(pb[j].z); d[3] = f2tf(pb[j].w);
            }
        } else {
#pragma unroll
            for (int j = 0; j < 4; j++) {
                Bs[(lbn + 4 * j + 0) * 36 + lbk] = f2tf(pb[j].x);
                Bs[(lbn + 4 * j + 1) * 36 + lbk] = f2tf(pb[j].y);
                Bs[(lbn + 4 * j + 2) * 36 + lbk] = f2tf(pb[j].z);
                Bs[(lbn + 4 * j + 3) * 36 + lbk] = f2tf(pb[j].w);
            }
        }
        __syncthreads();

        // prefetch next tiles (issued before compute to overlap)
        if (k0 + 32 < K) {
            Ap += 32;
            Bp += TRB ? 32 : (long)32 * N;
#pragma unroll
            for (int j = 0; j < 4; j++) {
                pa[j] = *(const float4*)(Ap + 4 * j);
                pb[j] = *(const float4*)(Bp + 4 * j);
            }
        }

#pragma unroll
        for (int ks = 0; ks < 4; ks++) {
            const int kb = ks * 8 + (lane & 3);
            unsigned af[2][4], bf[8][2];
#pragma unroll
            for (int mi = 0; mi < 2; mi++) {
                int r = wm + mi * 16 + (lane >> 2);
                af[mi][0] = As[r * 36 + kb];
                af[mi][1] = As[(r + 8) * 36 + kb];
                af[mi][2] = As[r * 36 + kb + 4];
                af[mi][3] = As[(r + 8) * 36 + kb + 4];
            }
#pragma unroll
            for (int ni = 0; ni < 8; ni++) {
                int c = wn + ni * 8 + (lane >> 2);
                bf[ni][0] = Bs[c * 36 + kb];
                bf[ni][1] = Bs[c * 36 + kb + 4];
            }
#pragma unroll
            for (int mi = 0; mi < 2; mi++)
#pragma unroll
                for (int ni = 0; ni < 8; ni++) {
                    asm volatile(
                        "mma.sync.aligned.m16n8k8.row.col.f32.tf32.tf32.f32 "
                        "{%0,%1,%2,%3}, {%4,%5,%6,%7}, {%8,%9}, {%0,%1,%2,%3};\n"
                        : "+f"(acc[mi][ni][0]), "+f"(acc[mi][ni][1]),
                          "+f"(acc[mi][ni][2]), "+f"(acc[mi][ni][3])
                        : "r"(af[mi][0]), "r"(af[mi][1]),
                          "r"(af[mi][2]), "r"(af[mi][3]),
                          "r"(bf[ni][0]), "r"(bf[ni][1]));
                }
        }
        __syncthreads();
    }

#pragma unroll
    for (int mi = 0; mi < 2; mi++)
#pragma unroll
        for (int ni = 0; ni < 8; ni++) {
            int r = m0 + wm + mi * 16 + (lane >> 2);
            int c = n0 + wn + ni * 8 + 2 * (lane & 3);
            *(float2*)&C[(long)r * N + c] =
                make_float2(acc[mi][ni][0], acc[mi][ni][1]);
            *(float2*)&C[(long)(r + 8) * N + c] =
                make_float2(acc[mi][ni][2], acc[mi][ni][3]);
        }
}

// ---------------- image QKV transform: RMSNorm + RoPE + layout --------------
__global__ void __launch_bounds__(256) transform_img(
    const float* __restrict__ rope, const float* __restrict__ gq,
    const float* __restrict__ gk)
{
    int r    = blockIdx.x * 8 + (threadIdx.x >> 5);
    int lane = threadIdx.x & 31;
    int h  = r & (NH - 1);
    int bl = r >> 4;
    int l  = bl & (LIMG - 1);
    int b  = bl >> 11;
    int d  = lane * 4;

    const float* row = g_qkv_raw + (long)bl * (3 * DMODEL) + h * DHD;
    float4 q = *(const float4*)&row[d];
    float4 k = *(const float4*)&row[DMODEL + d];
    float4 v = *(const float4*)&row[2 * DMODEL + d];

    float sq = q.x * q.x + q.y * q.y + q.z * q.z + q.w * q.w;
    float sk = k.x * k.x + k.y * k.y + k.z * k.z + k.w * k.w;
#pragma unroll
    for (int o = 16; o; o >>= 1) {
        sq += __shfl_xor_sync(0xffffffffu, sq, o);
        sk += __shfl_xor_sync(0xffffffffu, sk, o);
    }
    float rq = rsqrtf(sq * (1.f / DHD) + EPSV);
    float rk = rsqrtf(sk * (1.f / DHD) + EPSV);

    float4 wq = *(const float4*)&gq[d];
    float4 wk = *(const float4*)&gk[d];
    q.x *= rq * wq.x; q.y *= rq * wq.y; q.z *= rq * wq.z; q.w *= rq * wq.w;
    k.x *= rk * wk.x; k.y *= rk * wk.y; k.z *= rk * wk.z; k.w *= rk * wk.w;

    const float* fc = rope + (((long)bl) * 64 + lane * 2) * 4;
    float4 f0 = *(const float4*)fc;
    float4 f1 = *(const float4*)(fc + 4);

    float4 qo, ko;
    qo.x = f0.x * q.x + f0.y * q.y;  qo.y = f0.z * q.x + f0.w * q.y;
    qo.z = f1.x * q.z + f1.y * q.w;  qo.w = f1.z * q.z + f1.w * q.w;
    ko.x = f0.x * k.x + f0.y * k.y;  ko.y = f0.z * k.x + f0.w * k.y;
    ko.z = f1.x * k.z + f1.y * k.w;  ko.w = f1.z * k.z + f1.w * k.w;

    // fold softmax scale into Q
    qo.x *= SCALE; qo.y *= SCALE; qo.z *= SCALE; qo.w *= SCALE;

    long qi = (((long)(b * NH + h)) * LIMG + l) * DHD + d;
    *(float4*)&g_qbuf[qi] = qo;
    long ki = (((long)(b * NH + h)) * LKTOT + (LTXT + l)) * DHD + d;
    *(float4*)&g_kbuf[ki] = ko;
    *(float4*)&g_vbuf[ki] = v;
}

// ---------------- text KV transform: RMSNorm(k) + layout --------------------
__global__ void __launch_bounds__(256) transform_txt(const float* __restrict__ gak)
{
    int r    = blockIdx.x * 8 + (threadIdx.x >> 5);
    int lane = threadIdx.x & 31;
    int h  = r & (NH - 1);
    int bl = r >> 4;
    int l  = bl & (LTXT - 1);
    int b  = bl >> 9;
    int d  = lane * 4;

    const float* row = g_kv_raw + (long)bl * (2 * DMODEL) + h * DHD;
    float4 k = *(const float4*)&row[d];
    float4 v = *(const float4*)&row[DMODEL + d];

    float sk = k.x * k.x + k.y * k.y + k.z * k.z + k.w * k.w;
#pragma unroll
    for (int o = 16; o; o >>= 1) sk += __shfl_xor_sync(0xffffffffu, sk, o);
    float rk = rsqrtf(sk * (1.f / DHD) + EPSV);

    float4 wk = *(const float4*)&gak[d];
    k.x *= rk * wk.x; k.y *= rk * wk.y; k.z *= rk * wk.z; k.w *= rk * wk.w;

    long ki = (((long)(b * NH + h)) * LKTOT + l) * DHD + d;
    *(float4*)&g_kbuf[ki] = k;
    *(float4*)&g_vbuf[ki] = v;
}

// ---------------- mask lengths (dtype-agnostic: bool(1B) or int32) ----------
__global__ void lengths_kernel(const unsigned char* __restrict__ mask)
{
    __shared__ int red[256];
    int b = blockIdx.x;
    int es = (mask[1] != 0) ? 1 : 4;
    int nbytes = LTXT * es;
    const unsigned char* p = mask + (long)b * nbytes;
    int c = 0;
    for (int i = threadIdx.x; i < nbytes; i += 256) c += (p[i] != 0);
    red[threadIdx.x] = c;
    __syncthreads();
    for (int o = 128; o; o >>= 1) {
        if (threadIdx.x < o) red[threadIdx.x] += red[threadIdx.x + o];
        __syncthreads();
    }
    if (threadIdx.x == 0) g_len[b] = red[0];
}

// ---------------- masked softmax over scores rows (in place) ----------------
__global__ void __launch_bounds__(256) softmax_kernel()
{
    long row = blockIdx.x;
    int b = (int)(row >> 15);
    float* p = g_scores + row * (long)LKTOT;
    int len = g_len[b];
    int t = threadIdx.x;

    float vals[10];
    float m = -INFINITY;
#pragma unroll
    for (int j = 0; j < 10; j++) {
        int i = t + j * 256;
        float x = p[i];
        bool valid = (i >= LTXT) || (i < len);
        x = valid ? x : -INFINITY;
        vals[j] = x;
        m = fmaxf(m, x);
    }
    __shared__ float red[256];
    red[t] = m; __syncthreads();
    for (int o = 128; o; o >>= 1) {
        if (t < o) red[t] = fmaxf(red[t], red[t + o]);
        __syncthreads();
    }
    m = red[0]; __syncthreads();

    float s = 0.f;
#pragma unroll
    for (int j = 0; j < 10; j++) {
        float e = __expf(vals[j] - m);
        vals[j] = e;
        s += e;
    }
    red[t] = s; __syncthreads();
    for (int o = 128; o; o >>= 1) {
        if (t < o) red[t] += red[t + o];
        __syncthreads();
    }
    float inv = 1.f / red[0];
#pragma unroll
    for (int j = 0; j < 10; j++) p[t + j * 256] = vals[j] * inv;
}

// ---------------- [B,H,L,DH] -> [B,L,H*DH] repack ---------------------------
__global__ void __launch_bounds__(128) repack_kernel()
{
    int r = blockIdx.x;
    int t = threadIdx.x;
    int b = r >> 15;
    int h = (r >> 11) & (NH - 1);
    int l = r & (LIMG - 1);
    long oi = (((long)(b * LIMG + l)) * NH + h) * DHD + t;
    g_attn2[oi] = g_attn_raw[(long)r * DHD + t];
}

// ---------------- launch ----------------------------------------------------
extern "C" void kernel_launch(void* const* d_in, const int* in_sizes, int n_in,
                              void* d_out, int out_size)
{
    const float* hidden = (const float*)d_in[0];
    const float* enc    = (const float*)d_in[1];
    const unsigned char* mask = (const unsigned char*)d_in[2];
    const float* rope   = (const float*)d_in[3];
    const float* w_qkv  = (const float*)d_in[4];
    const float* w_kv   = (const float*)d_in[5];
    const float* w_o    = (const float*)d_in[6];
    const float* gq     = (const float*)d_in[7];
    const float* gk     = (const float*)d_in[8];
    const float* gak    = (const float*)d_in[9];
    float* out = (float*)d_out;

    float *qkv_raw, *kv_raw, *qbuf, *kbuf, *vbuf, *scores, *attn_raw, *attn2;
    cudaGetSymbolAddress((void**)&qkv_raw,  g_qkv_raw);
    cudaGetSymbolAddress((void**)&kv_raw,   g_kv_raw);
    cudaGetSymbolAddress((void**)&qbuf,     g_qbuf);
    cudaGetSymbolAddress((void**)&kbuf,     g_kbuf);
    cudaGetSymbolAddress((void**)&vbuf,     g_vbuf);
    cudaGetSymbolAddress((void**)&scores,   g_scores);
    cudaGetSymbolAddress((void**)&attn_raw, g_attn_raw);
    cudaGetSymbolAddress((void**)&attn2,    g_attn2);

    dim3 blk(256);

    // 1) image QKV projection: [4096,2048]@[2048,6144]
    gemm_tf32<false><<<dim3(6144 / 128, 4096 / 128, 1), blk>>>(
        hidden, w_qkv, qkv_raw, 4096, 6144, 2048, 0, 0, 0);
    // 2) text KV projection: [1024,2048]@[2048,4096]
    gemm_tf32<false><<<dim3(4096 / 128, 1024 / 128, 1), blk>>>(
        enc, w_kv, kv_raw, 1024, 4096, 2048, 0, 0, 0);
    // 3) transforms
    transform_img<<<BB * LIMG * NH / 8, blk>>>(rope, gq, gk);
    transform_txt<<<BB * LTXT * NH / 8, blk>>>(gak);
    lengths_kernel<<<BB, blk>>>(mask);
    // 4) scores = Q @ K^T (scale pre-folded into Q), batched over 32 (b,h)
    gemm_tf32<true><<<dim3(LKTOT / 128, LIMG / 128, BB * NH), blk>>>(
        qbuf, kbuf, scores, LIMG, LKTOT, DHD,
        (long)LIMG * DHD, (long)LKTOT * DHD, (long)LIMG * LKTOT);
    // 5) masked softmax
    softmax_kernel<<<BB * NH * LIMG, blk>>>();
    // 6) attn = P @ V, batched
    gemm_tf32<false><<<dim3(1, LIMG / 128, BB * NH), blk>>>(
        scores, vbuf, attn_raw, LIMG, DHD, LKTOT,
        (long)LIMG * LKTOT, (long)LKTOT * DHD, (long)LIMG * DHD);
    // 7) repack to [B, L, H*DH]
    repack_kernel<<<BB * NH * LIMG, 128>>>();
    // 8) output projection: [4096,2048]@[2048,2048]
    gemm_tf32<false><<<dim3(2048 / 128, 4096 / 128, 1), blk>>>(
        attn2, w_o, out, 4096, 2048, 2048, 0, 0, 0);
}

// round 4
// speedup vs baseline: 2.1185x; 1.0513x over previous
#include <cuda_runtime.h>
#include <cuda_bf16.h>
#include <math.h>

#define BB 2
#define LIMG 2048
#define LTXT 512
#define DMODEL 2048
#define NH 16
#define DHD 128
#define LKTOT (LTXT + LIMG)   // 2560
#define EPSV 1e-6f
#define SCALE 0.08838834764831845f  // 1/sqrt(128)

// flash tiling
#define QT 64
#define KT 128
#define STR 132                 // smem row stride (u32 words); 132 % 32 = 4
#define NKV (LKTOT / KT)        // 20
#define FLASH_SMEM ((2 * QT * STR + 2 * KT * STR) * 4 + QT * 4 * 4)

// ---------------- scratch (device globals; no allocations allowed) ----------
__device__ float g_qkv_raw[BB * LIMG * 3 * DMODEL];
__device__ float g_kv_raw[BB * LTXT * 2 * DMODEL];
__device__ float g_qbuf[BB * NH * LIMG * DHD];
__device__ float g_kbuf[BB * NH * LKTOT * DHD];
__device__ float g_vbuf[BB * NH * LKTOT * DHD];
__device__ float g_attn2[BB * LIMG * NH * DHD];
__device__ int   g_len[BB];

__device__ __forceinline__ unsigned f2tf(float x) {
    unsigned u;
    asm("cvt.rna.tf32.f32 %0, %1;" : "=r"(u) : "f"(x));
    return u;
}

__device__ __forceinline__ void mma8(float* c, unsigned a0, unsigned a1,
                                     unsigned a2, unsigned a3,
                                     unsigned b0, unsigned b1) {
    asm volatile(
        "mma.sync.aligned.m16n8k8.row.col.f32.tf32.tf32.f32 "
        "{%0,%1,%2,%3}, {%4,%5,%6,%7}, {%8,%9}, {%0,%1,%2,%3};\n"
        : "+f"(c[0]), "+f"(c[1]), "+f"(c[2]), "+f"(c[3])
        : "r"(a0), "r"(a1), "r"(a2), "r"(a3), "r"(b0), "r"(b1));
}

// ---------------- TF32 tensor-core GEMM: C = A @ B ---------------------------
__global__ void __launch_bounds__(256) gemm_tf32(
    const float* __restrict__ A, const float* __restrict__ B,
    float* __restrict__ C, int M, int N, int K)
{
    __shared__ unsigned As[128 * 36];
    __shared__ unsigned Bs[128 * 36];

    const int t    = threadIdx.x;
    const int lane = t & 31;
    const int warp = t >> 5;
    const int wm   = (warp >> 1) * 32;
    const int wn   = (warp & 1) * 64;
    const int m0   = blockIdx.y * 128;
    const int n0   = blockIdx.x * 128;

    const int lar = t >> 1;
    const int lak = (t & 1) * 16;
    const int lbk = t >> 3;
    const int lbn = (t & 7) * 16;

    float acc[2][8][4];
#pragma unroll
    for (int i = 0; i < 2; i++)
#pragma unroll
        for (int j = 0; j < 8; j++)
#pragma unroll
            for (int c = 0; c < 4; c++) acc[i][j][c] = 0.f;

    const float* Ap = A + (long)(m0 + lar) * K + lak;
    const float* Bp = B + (long)lbk * N + n0 + lbn;

    float4 pa[4], pb[4];
#pragma unroll
    for (int j = 0; j < 4; j++) {
        pa[j] = *(const float4*)(Ap + 4 * j);
        pb[j] = *(const float4*)(Bp + 4 * j);
    }

    for (int k0 = 0; k0 < K; k0 += 32) {
#pragma unroll
        for (int j = 0; j < 4; j++) {
            unsigned* d = &As[lar * 36 + lak + 4 * j];
            d[0] = f2tf(pa[j].x); d[1] = f2tf(pa[j].y);
            d[2] = f2tf(pa[j].z); d[3] = f2tf(pa[j].w);
        }
#pragma unroll
        for (int j = 0; j < 4; j++) {
            Bs[(lbn + 4 * j + 0) * 36 + lbk] = f2tf(pb[j].x);
            Bs[(lbn + 4 * j + 1) * 36 + lbk] = f2tf(pb[j].y);
            Bs[(lbn + 4 * j + 2) * 36 + lbk] = f2tf(pb[j].z);
            Bs[(lbn + 4 * j + 3) * 36 + lbk] = f2tf(pb[j].w);
        }
        __syncthreads();

        if (k0 + 32 < K) {
            Ap += 32;
            Bp += (long)32 * N;
#pragma unroll
            for (int j = 0; j < 4; j++) {
                pa[j] = *(const float4*)(Ap + 4 * j);
                pb[j] = *(const float4*)(Bp + 4 * j);
            }
        }

#pragma unroll
        for (int ks = 0; ks < 4; ks++) {
            const int kb = ks * 8 + (lane & 3);
            unsigned af[2][4], bf[8][2];
#pragma unroll
            for (int mi = 0; mi < 2; mi++) {
                int r = wm + mi * 16 + (lane >> 2);
                af[mi][0] = As[r * 36 + kb];
                af[mi][1] = As[(r + 8) * 36 + kb];
                af[mi][2] = As[r * 36 + kb + 4];
                af[mi][3] = As[(r + 8) * 36 + kb + 4];
            }
#pragma unroll
            for (int ni = 0; ni < 8; ni++) {
                int c = wn + ni * 8 + (lane >> 2);
                bf[ni][0] = Bs[c * 36 + kb];
                bf[ni][1] = Bs[c * 36 + kb + 4];
            }
#pragma unroll
            for (int mi = 0; mi < 2; mi++)
#pragma unroll
                for (int ni = 0; ni < 8; ni++)
                    mma8(acc[mi][ni], af[mi][0], af[mi][1], af[mi][2], af[mi][3],
                         bf[ni][0], bf[ni][1]);
        }
        __syncthreads();
    }

#pragma unroll
    for (int mi = 0; mi < 2; mi++)
#pragma unroll
        for (int ni = 0; ni < 8; ni++) {
            int r = m0 + wm + mi * 16 + (lane >> 2);
            int c = n0 + wn + ni * 8 + 2 * (lane & 3);
            *(float2*)&C[(long)r * N + c] =
                make_float2(acc[mi][ni][0], acc[mi][ni][1]);
            *(float2*)&C[(long)(r + 8) * N + c] =
                make_float2(acc[mi][ni][2], acc[mi][ni][3]);
        }
}

// ---------------- flash attention (tf32 mma, online softmax) ----------------
// grid (LIMG/QT, B*NH), 256 threads = 8 warps as 4(m) x 2(n).
__global__ void __launch_bounds__(256) flash_kernel()
{
    extern __shared__ unsigned sm[];
    unsigned* Qs = sm;                       // QT * STR
    unsigned* Ks = Qs + QT * STR;            // KT * STR
    unsigned* Vs = Ks + KT * STR;            // KT * STR
    unsigned* Ps = Vs + KT * STR;            // QT * STR
    float* redm = (float*)(Ps + QT * STR);   // QT * 2
    float* reds = redm + QT * 2;             // QT * 2

    const int bh = blockIdx.y;
    const int b  = bh >> 4;
    const int h  = bh & (NH - 1);
    const int q0 = blockIdx.x * QT;
    const int len = g_len[b];

    const int t = threadIdx.x, lane = t & 31, warp = t >> 5;
    const int wm  = (warp >> 1) * 16;        // 0,16,32,48
    const int wnid = warp & 1;
    const int wn  = wnid * 64;

    const float* Qg = g_qbuf + ((long)bh * LIMG + q0) * DHD;
    const float* Kg = g_kbuf + (long)bh * LKTOT * DHD;
    const float* Vg = g_vbuf + (long)bh * LKTOT * DHD;

    // load Q tile (64 x 128), convert to tf32
    for (int i = t * 4; i < QT * DHD; i += 256 * 4) {
        int r = i >> 7, d = i & 127;
        float4 v = *(const float4*)(Qg + (long)r * DHD + d);
        unsigned* dst = &Qs[r * STR + d];
        dst[0] = f2tf(v.x); dst[1] = f2tf(v.y);
        dst[2] = f2tf(v.z); dst[3] = f2tf(v.w);
    }

    const int rq = lane >> 2;       // local row within m16 tile
    float m0r = -INFINITY, m1r = -INFINITY;
    float l0 = 0.f, l1 = 0.f;
    float o[8][4];
#pragma unroll
    for (int ni = 0; ni < 8; ni++)
#pragma unroll
        for (int c = 0; c < 4; c++) o[ni][c] = 0.f;

    for (int j = 0; j < NKV; j++) {
        const int kvb = j * KT;
        __syncthreads();   // prev iter's mma done before K/V/Ps overwrite
        // load K,V tiles (128 x 128 each)
        for (int i = t * 4; i < KT * DHD; i += 256 * 4) {
            int r = i >> 7, d = i & 127;
            float4 kv = *(const float4*)(Kg + (long)(kvb + r) * DHD + d);
            float4 vv = *(const float4*)(Vg + (long)(kvb + r) * DHD + d);
            unsigned* dk = &Ks[r * STR + d];
            dk[0] = f2tf(kv.x); dk[1] = f2tf(kv.y);
            dk[2] = f2tf(kv.z); dk[3] = f2tf(kv.w);
            unsigned* dv = &Vs[r * STR + d];
            dv[0] = f2tf(vv.x); dv[1] = f2tf(vv.y);
            dv[2] = f2tf(vv.z); dv[3] = f2tf(vv.w);
        }
        __syncthreads();

        // S = Q K^T  (16 x 64 per warp)
        float s[8][4];
#pragma unroll
        for (int ni = 0; ni < 8; ni++)
#pragma unroll
            for (int c = 0; c < 4; c++) s[ni][c] = 0.f;

#pragma unroll
        for (int ks = 0; ks < 16; ks++) {
            const int kb = ks * 8 + (lane & 3);
            unsigned a0 = Qs[(wm + rq) * STR + kb];
            unsigned a1 = Qs[(wm + 8 + rq) * STR + kb];
            unsigned a2 = Qs[(wm + rq) * STR + kb + 4];
            unsigned a3 = Qs[(wm + 8 + rq) * STR + kb + 4];
#pragma unroll
            for (int ni = 0; ni < 8; ni++) {
                int nn = wn + ni * 8 + rq;
                unsigned b0 = Ks[nn * STR + kb];
                unsigned b1 = Ks[nn * STR + kb + 4];
                mma8(s[ni], a0, a1, a2, a3, b0, b1);
            }
        }

        // mask text region
        if (kvb < LTXT) {
#pragma unroll
            for (int ni = 0; ni < 8; ni++) {
                int col0 = kvb + wn + ni * 8 + 2 * (lane & 3);
                if (col0 >= len)     { s[ni][0] = -INFINITY; s[ni][2] = -INFINITY; }
                if (col0 + 1 >= len) { s[ni][1] = -INFINITY; s[ni][3] = -INFINITY; }
            }
        }

        // row max (partial over this warp's 64 cols)
        float pm0 = -INFINITY, pm1 = -INFINITY;
#pragma unroll
        for (int ni = 0; ni < 8; ni++) {
            pm0 = fmaxf(pm0, fmaxf(s[ni][0], s[ni][1]));
            pm1 = fmaxf(pm1, fmaxf(s[ni][2], s[ni][3]));
        }
        pm0 = fmaxf(pm0, __shfl_xor_sync(0xffffffffu, pm0, 1));
        pm0 = fmaxf(pm0, __shfl_xor_sync(0xffffffffu, pm0, 2));
        pm1 = fmaxf(pm1, __shfl_xor_sync(0xffffffffu, pm1, 1));
        pm1 = fmaxf(pm1, __shfl_xor_sync(0xffffffffu, pm1, 2));
        if ((lane & 3) == 0) {
            redm[(wm + rq) * 2 + wnid]     = pm0;
            redm[(wm + 8 + rq) * 2 + wnid] = pm1;
        }
        __syncthreads();
        float tm0 = fmaxf(redm[(wm + rq) * 2],     redm[(wm + rq) * 2 + 1]);
        float tm1 = fmaxf(redm[(wm + 8 + rq) * 2], redm[(wm + 8 + rq) * 2 + 1]);
        float mn0 = fmaxf(m0r, tm0);
        float mn1 = fmaxf(m1r, tm1);
        float al0 = __expf(m0r - mn0);
        float al1 = __expf(m1r - mn1);
        m0r = mn0; m1r = mn1;

        // p = exp(s - m), partial row sums, store P to smem (tf32)
        float ps0 = 0.f, ps1 = 0.f;
#pragma unroll
        for (int ni = 0; ni < 8; ni++) {
            float p0 = __expf(s[ni][0] - mn0);
            float p1 = __expf(s[ni][1] - mn0);
            float p2 = __expf(s[ni][2] - mn1);
            float p3 = __expf(s[ni][3] - mn1);
            ps0 += p0 + p1;
            ps1 += p2 + p3;
            int cc = wn + ni * 8 + 2 * (lane & 3);
            unsigned* d0 = &Ps[(wm + rq) * STR + cc];
            d0[0] = f2tf(p0); d0[1] = f2tf(p1);
            unsigned* d1 = &Ps[(wm + 8 + rq) * STR + cc];
            d1[0] = f2tf(p2); d1[1] = f2tf(p3);
        }
        ps0 += __shfl_xor_sync(0xffffffffu, ps0, 1);
        ps0 += __shfl_xor_sync(0xffffffffu, ps0, 2);
        ps1 += __shfl_xor_sync(0xffffffffu, ps1, 1);
        ps1 += __shfl_xor_sync(0xffffffffu, ps1, 2);
        if ((lane & 3) == 0) {
            reds[(wm + rq) * 2 + wnid]     = ps0;
            reds[(wm + 8 + rq) * 2 + wnid] = ps1;
        }

        // rescale O while waiting
#pragma unroll
        for (int ni = 0; ni < 8; ni++) {
            o[ni][0] *= al0; o[ni][1] *= al0;
            o[ni][2] *= al1; o[ni][3] *= al1;
        }
        __syncthreads();
        l0 = l0 * al0 + reds[(wm + rq) * 2]     + reds[(wm + rq) * 2 + 1];
        l1 = l1 * al1 + reds[(wm + 8 + rq) * 2] + reds[(wm + 8 + rq) * 2 + 1];

        // O += P @ V   (contract over 128 kv)
#pragma unroll
        for (int ks = 0; ks < 16; ks++) {
            const int kb = ks * 8 + (lane & 3);
            unsigned a0 = Ps[(wm + rq) * STR + kb];
            unsigned a1 = Ps[(wm + 8 + rq) * STR + kb];
            unsigned a2 = Ps[(wm + rq) * STR + kb + 4];
            unsigned a3 = Ps[(wm + 8 + rq) * STR + kb + 4];
#pragma unroll
            for (int ni = 0; ni < 8; ni++) {
                int dd = wn + ni * 8 + rq;
                unsigned b0 = Vs[kb * STR + dd];
                unsigned b1 = Vs[(kb + 4) * STR + dd];
                mma8(o[ni], a0, a1, a2, a3, b0, b1);
            }
        }
    }

    // epilogue: divide by l, write directly to [B, L, H*DH]
    float inv0 = 1.f / l0, inv1 = 1.f / l1;
    int row0 = q0 + wm + rq;
#pragma unroll
    for (int ni = 0; ni < 8; ni++) {
        int cc = h * DHD + wn + ni * 8 + 2 * (lane & 3);
        *(float2*)&g_attn2[((long)(b * LIMG + row0)) * (NH * DHD) + cc] =
            make_float2(o[ni][0] * inv0, o[ni][1] * inv0);
        *(float2*)&g_attn2[((long)(b * LIMG + row0 + 8)) * (NH * DHD) + cc] =
            make_float2(o[ni][2] * inv1, o[ni][3] * inv1);
    }
}

// ---------------- image QKV transform: RMSNorm + RoPE + layout --------------
__global__ void __launch_bounds__(256) transform_img(
    const float* __restrict__ rope, const float* __restrict__ gq,
    const float* __restrict__ gk)
{
    int r    = blockIdx.x * 8 + (threadIdx.x >> 5);
    int lane = threadIdx.x & 31;
    int h  = r & (NH - 1);
    int bl = r >> 4;
    int l  = bl & (LIMG - 1);
    int b  = bl >> 11;
    int d  = lane * 4;

    const float* row = g_qkv_raw + (long)bl * (3 * DMODEL) + h * DHD;
    float4 q = *(const float4*)&row[d];
    float4 k = *(const float4*)&row[DMODEL + d];
    float4 v = *(const float4*)&row[2 * DMODEL + d];

    float sq = q.x * q.x + q.y * q.y + q.z * q.z + q.w * q.w;
    float sk = k.x * k.x + k.y * k.y + k.z * k.z + k.w * k.w;
#pragma unroll
    for (int o = 16; o; o >>= 1) {
        sq += __shfl_xor_sync(0xffffffffu, sq, o);
        sk += __shfl_xor_sync(0xffffffffu, sk, o);
    }
    float rq = rsqrtf(sq * (1.f / DHD) + EPSV);
    float rk = rsqrtf(sk * (1.f / DHD) + EPSV);

    float4 wq = *(const float4*)&gq[d];
    float4 wk = *(const float4*)&gk[d];
    q.x *= rq * wq.x; q.y *= rq * wq.y; q.z *= rq * wq.z; q.w *= rq * wq.w;
    k.x *= rk * wk.x; k.y *= rk * wk.y; k.z *= rk * wk.z; k.w *= rk * wk.w;

    const float* fc = rope + (((long)bl) * 64 + lane * 2) * 4;
    float4 f0 = *(const float4*)fc;
    float4 f1 = *(const float4*)(fc + 4);

    float4 qo, ko;
    qo.x = f0.x * q.x + f0.y * q.y;  qo.y = f0.z * q.x + f0.w * q.y;
    qo.z = f1.x * q.z + f1.y * q.w;  qo.w = f1.z * q.z + f1.w * q.w;
    ko.x = f0.x * k.x + f0.y * k.y;  ko.y = f0.z * k.x + f0.w * k.y;
    ko.z = f1.x * k.z + f1.y * k.w;  ko.w = f1.z * k.z + f1.w * k.w;

    qo.x *= SCALE; qo.y *= SCALE; qo.z *= SCALE; qo.w *= SCALE;

    long qi = (((long)(b * NH + h)) * LIMG + l) * DHD + d;
    *(float4*)&g_qbuf[qi] = qo;
    long ki = (((long)(b * NH + h)) * LKTOT + (LTXT + l)) * DHD + d;
    *(float4*)&g_kbuf[ki] = ko;
    *(float4*)&g_vbuf[ki] = v;
}

// ---------------- text KV transform: RMSNorm(k) + layout --------------------
__global__ void __launch_bounds__(256) transform_txt(const float* __restrict__ gak)
{
    int r    = blockIdx.x * 8 + (threadIdx.x >> 5);
    int lane = threadIdx.x & 31;
    int h  = r & (NH - 1);
    int bl = r >> 4;
    int l  = bl & (LTXT - 1);
    int b  = bl >> 9;
    int d  = lane * 4;

    const float* row = g_kv_raw + (long)bl * (2 * DMODEL) + h * DHD;
    float4 k = *(const float4*)&row[d];
    float4 v = *(const float4*)&row[DMODEL + d];

    float sk = k.x * k.x + k.y * k.y + k.z * k.z + k.w * k.w;
#pragma unroll
    for (int o = 16; o; o >>= 1) sk += __shfl_xor_sync(0xffffffffu, sk, o);
    float rk = rsqrtf(sk * (1.f / DHD) + EPSV);

    float4 wk = *(const float4*)&gak[d];
    k.x *= rk * wk.x; k.y *= rk * wk.y; k.z *= rk * wk.z; k.w *= rk * wk.w;

    long ki = (((long)(b * NH + h)) * LKTOT + l) * DHD + d;
    *(float4*)&g_kbuf[ki] = k;
    *(float4*)&g_vbuf[ki] = v;
}

// ---------------- mask lengths (dtype-agnostic: bool(1B) or int32) ----------
__global__ void lengths_kernel(const unsigned char* __restrict__ mask)
{
    __shared__ int red[256];
    int b = blockIdx.x;
    int es = (mask[1] != 0) ? 1 : 4;
    int nbytes = LTXT * es;
    const unsigned char* p = mask + (long)b * nbytes;
    int c = 0;
    for (int i = threadIdx.x; i < nbytes; i += 256) c += (p[i] != 0);
    red[threadIdx.x] = c;
    __syncthreads();
    for (int o = 128; o; o >>= 1) {
        if (threadIdx.x < o) red[threadIdx.x] += red[threadIdx.x + o];
        __syncthreads();
    }
    if (threadIdx.x == 0) g_len[b] = red[0];
}

// ---------------- launch ----------------------------------------------------
extern "C" void kernel_launch(void* const* d_in, const int* in_sizes, int n_in,
                              void* d_out, int out_size)
{
    const float* hidden = (const float*)d_in[0];
    const float* enc    = (const float*)d_in[1];
    const unsigned char* mask = (const unsigned char*)d_in[2];
    const float* rope   = (const float*)d_in[3];
    const float* w_qkv  = (const float*)d_in[4];
    const float* w_kv   = (const float*)d_in[5];
    const float* w_o    = (const float*)d_in[6];
    const float* gq     = (const float*)d_in[7];
    const float* gk     = (const float*)d_in[8];
    const float* gak    = (const float*)d_in[9];
    float* out = (float*)d_out;

    float *qkv_raw, *kv_raw, *attn2;
    cudaGetSymbolAddress((void**)&qkv_raw, g_qkv_raw);
    cudaGetSymbolAddress((void**)&kv_raw,  g_kv_raw);
    cudaGetSymbolAddress((void**)&attn2,   g_attn2);

    static int smem_set = 0;
    if (!smem_set) {
        cudaFuncSetAttribute(flash_kernel,
                             cudaFuncAttributeMaxDynamicSharedMemorySize,
                             FLASH_SMEM);
        smem_set = 1;
    }

    dim3 blk(256);

    // 1) image QKV projection: [4096,2048]@[2048,6144]
    gemm_tf32<<<dim3(6144 / 128, 4096 / 128, 1), blk>>>(
        hidden, w_qkv, qkv_raw, 4096, 6144, 2048);
    // 2) text KV projection: [1024,2048]@[2048,4096]
    gemm_tf32<<<dim3(4096 / 128, 1024 / 128, 1), blk>>>(
        enc, w_kv, kv_raw, 1024, 4096, 2048);
    // 3) transforms + mask lengths
    transform_img<<<BB * LIMG * NH / 8, blk>>>(rope, gq, gk);
    transform_txt<<<BB * LTXT * NH / 8, blk>>>(gak);
    lengths_kernel<<<BB, blk>>>(mask);
    // 4) fused flash attention -> g_attn2 in [B, L, H*DH]
    flash_kernel<<<dim3(LIMG / QT, BB * NH), blk, FLASH_SMEM>>>();
    // 5) output projection: [4096,2048]@[2048,2048]
    gemm_tf32<<<dim3(2048 / 128, 4096 / 128, 1), blk>>>(
        attn2, w_o, out, 4096, 2048, 2048);
}

// round 5
// speedup vs baseline: 2.1196x; 1.0005x over previous
#include <cuda_runtime.h>
#include <cuda_bf16.h>
#include <math.h>

#define BB 2
#define LIMG 2048
#define LTXT 512
#define DMODEL 2048
#define NH 16
#define DHD 128
#define LKTOT (LTXT + LIMG)   // 2560
#define EPSV 1e-6f
#define SCALE 0.08838834764831845f  // 1/sqrt(128)

// flash tiling
#define QT 64
#define KT 128
#define STR 132                 // smem row stride (u32 words); 132 % 32 = 4
#define NKV (LKTOT / KT)        // 20
#define FLASH_SMEM ((2 * QT * STR + 2 * KT * STR) * 4 + QT * 4 * 4)

// ---------------- scratch (device globals; no allocations allowed) ----------
__device__ float g_qkv_raw[BB * LIMG * 3 * DMODEL];
__device__ float g_kv_raw[BB * LTXT * 2 * DMODEL];
__device__ float g_qbuf[BB * NH * LIMG * DHD];
__device__ float g_kbuf[BB * NH * LKTOT * DHD];
__device__ float g_vbuf[BB * NH * LKTOT * DHD];
__device__ float g_attn2[BB * LIMG * NH * DHD];
__device__ int   g_len[BB];

__device__ __forceinline__ unsigned f2tf(float x) {
    unsigned u;
    asm("cvt.rna.tf32.f32 %0, %1;" : "=r"(u) : "f"(x));
    return u;
}

__device__ __forceinline__ void mma8(float* c, unsigned a0, unsigned a1,
                                     unsigned a2, unsigned a3,
                                     unsigned b0, unsigned b1) {
    asm volatile(
        "mma.sync.aligned.m16n8k8.row.col.f32.tf32.tf32.f32 "
        "{%0,%1,%2,%3}, {%4,%5,%6,%7}, {%8,%9}, {%0,%1,%2,%3};\n"
        : "+f"(c[0]), "+f"(c[1]), "+f"(c[2]), "+f"(c[3])
        : "r"(a0), "r"(a1), "r"(a2), "r"(a3), "r"(b0), "r"(b1));
}

// ---------------- TF32 tensor-core GEMM: C = A @ B ---------------------------
__global__ void __launch_bounds__(256) gemm_tf32(
    const float* __restrict__ A, const float* __restrict__ B,
    float* __restrict__ C, int M, int N, int K)
{
    __shared__ unsigned As[128 * 36];
    __shared__ unsigned Bs[128 * 36];

    const int t    = threadIdx.x;
    const int lane = t & 31;
    const int warp = t >> 5;
    const int wm   = (warp >> 1) * 32;
    const int wn   = (warp & 1) * 64;
    const int m0   = blockIdx.y * 128;
    const int n0   = blockIdx.x * 128;

    const int lar = t >> 1;
    const int lak = (t & 1) * 16;
    const int lbk = t >> 3;
    const int lbn = (t & 7) * 16;

    float acc[2][8][4];
#pragma unroll
    for (int i = 0; i < 2; i++)
#pragma unroll
        for (int j = 0; j < 8; j++)
#pragma unroll
            for (int c = 0; c < 4; c++) acc[i][j][c] = 0.f;

    const float* Ap = A + (long)(m0 + lar) * K + lak;
    const float* Bp = B + (long)lbk * N + n0 + lbn;

    float4 pa[4], pb[4];
#pragma unroll
    for (int j = 0; j < 4; j++) {
        pa[j] = *(const float4*)(Ap + 4 * j);
        pb[j] = *(const float4*)(Bp + 4 * j);
    }

    for (int k0 = 0; k0 < K; k0 += 32) {
#pragma unroll
        for (int j = 0; j < 4; j++) {
            unsigned* d = &As[lar * 36 + lak + 4 * j];
            d[0] = f2tf(pa[j].x); d[1] = f2tf(pa[j].y);
            d[2] = f2tf(pa[j].z); d[3] = f2tf(pa[j].w);
        }
#pragma unroll
        for (int j = 0; j < 4; j++) {
            Bs[(lbn + 4 * j + 0) * 36 + lbk] = f2tf(pb[j].x);
            Bs[(lbn + 4 * j + 1) * 36 + lbk] = f2tf(pb[j].y);
            Bs[(lbn + 4 * j + 2) * 36 + lbk] = f2tf(pb[j].z);
            Bs[(lbn + 4 * j + 3) * 36 + lbk] = f2tf(pb[j].w);
        }
        __syncthreads();

        if (k0 + 32 < K) {
            Ap += 32;
            Bp += (long)32 * N;
#pragma unroll
            for (int j = 0; j < 4; j++) {
                pa[j] = *(const float4*)(Ap + 4 * j);
                pb[j] = *(const float4*)(Bp + 4 * j);
            }
        }

#pragma unroll
        for (int ks = 0; ks < 4; ks++) {
            const int kb = ks * 8 + (lane & 3);
            unsigned af[2][4], bf[8][2];
#pragma unroll
            for (int mi = 0; mi < 2; mi++) {
                int r = wm + mi * 16 + (lane >> 2);
                af[mi][0] = As[r * 36 + kb];
                af[mi][1] = As[(r + 8) * 36 + kb];
                af[mi][2] = As[r * 36 + kb + 4];
                af[mi][3] = As[(r + 8) * 36 + kb + 4];
            }
#pragma unroll
            for (int ni = 0; ni < 8; ni++) {
                int c = wn + ni * 8 + (lane >> 2);
                bf[ni][0] = Bs[c * 36 + kb];
                bf[ni][1] = Bs[c * 36 + kb + 4];
            }
#pragma unroll
            for (int mi = 0; mi < 2; mi++)
#pragma unroll
                for (int ni = 0; ni < 8; ni++)
                    mma8(acc[mi][ni], af[mi][0], af[mi][1], af[mi][2], af[mi][3],
                         bf[ni][0], bf[ni][1]);
        }
        __syncthreads();
    }

#pragma unroll
    for (int mi = 0; mi < 2; mi++)
#pragma unroll
        for (int ni = 0; ni < 8; ni++) {
            int r = m0 + wm + mi * 16 + (lane >> 2);
            int c = n0 + wn + ni * 8 + 2 * (lane & 3);
            *(float2*)&C[(long)r * N + c] =
                make_float2(acc[mi][ni][0], acc[mi][ni][1]);
            *(float2*)&C[(long)(r + 8) * N + c] =
                make_float2(acc[mi][ni][2], acc[mi][ni][3]);
        }
}

// ---------------- flash attention (tf32 mma, online softmax) ----------------
// grid (LIMG/QT, B*NH), 256 threads = 8 warps as 4(m) x 2(n).
__global__ void __launch_bounds__(256) flash_kernel()
{
    extern __shared__ unsigned sm[];
    unsigned* Qs = sm;                       // QT * STR
    unsigned* Ks = Qs + QT * STR;            // KT * STR
    unsigned* Vs = Ks + KT * STR;            // KT * STR
    unsigned* Ps = Vs + KT * STR;            // QT * STR
    float* redm = (float*)(Ps + QT * STR);   // QT * 2
    float* reds = redm + QT * 2;             // QT * 2

    const int bh = blockIdx.y;
    const int b  = bh >> 4;
    const int h  = bh & (NH - 1);
    const int q0 = blockIdx.x * QT;
    const int len = g_len[b];

    const int t = threadIdx.x, lane = t & 31, warp = t >> 5;
    const int wm  = (warp >> 1) * 16;        // 0,16,32,48
    const int wnid = warp & 1;
    const int wn  = wnid * 64;

    const float* Qg = g_qbuf + ((long)bh * LIMG + q0) * DHD;
    const float* Kg = g_kbuf + (long)bh * LKTOT * DHD;
    const float* Vg = g_vbuf + (long)bh * LKTOT * DHD;

    // load Q tile (64 x 128), convert to tf32
    for (int i = t * 4; i < QT * DHD; i += 256 * 4) {
        int r = i >> 7, d = i & 127;
        float4 v = *(const float4*)(Qg + (long)r * DHD + d);
        unsigned* dst = &Qs[r * STR + d];
        dst[0] = f2tf(v.x); dst[1] = f2tf(v.y);
        dst[2] = f2tf(v.z); dst[3] = f2tf(v.w);
    }

    const int rq = lane >> 2;       // local row within m16 tile
    float m0r = -INFINITY, m1r = -INFINITY;
    float l0 = 0.f, l1 = 0.f;
    float o[8][4];
#pragma unroll
    for (int ni = 0; ni < 8; ni++)
#pragma unroll
        for (int c = 0; c < 4; c++) o[ni][c] = 0.f;

    for (int j = 0; j < NKV; j++) {
        const int kvb = j * KT;
        __syncthreads();   // prev iter's mma done before K/V/Ps overwrite
        // load K,V tiles (128 x 128 each)
        for (int i = t * 4; i < KT * DHD; i += 256 * 4) {
            int r = i >> 7, d = i & 127;
            float4 kv = *(const float4*)(Kg + (long)(kvb + r) * DHD + d);
            float4 vv = *(const float4*)(Vg + (long)(kvb + r) * DHD + d);
            unsigned* dk = &Ks[r * STR + d];
            dk[0] = f2tf(kv.x); dk[1] = f2tf(kv.y);
            dk[2] = f2tf(kv.z); dk[3] = f2tf(kv.w);
            unsigned* dv = &Vs[r * STR + d];
            dv[0] = f2tf(vv.x); dv[1] = f2tf(vv.y);
            dv[2] = f2tf(vv.z); dv[3] = f2tf(vv.w);
        }
        __syncthreads();

        // S = Q K^T  (16 x 64 per warp)
        float s[8][4];
#pragma unroll
        for (int ni = 0; ni < 8; ni++)
#pragma unroll
            for (int c = 0; c < 4; c++) s[ni][c] = 0.f;

#pragma unroll
        for (int ks = 0; ks < 16; ks++) {
            const int kb = ks * 8 + (lane & 3);
            unsigned a0 = Qs[(wm + rq) * STR + kb];
            unsigned a1 = Qs[(wm + 8 + rq) * STR + kb];
            unsigned a2 = Qs[(wm + rq) * STR + kb + 4];
            unsigned a3 = Qs[(wm + 8 + rq) * STR + kb + 4];
#pragma unroll
            for (int ni = 0; ni < 8; ni++) {
                int nn = wn + ni * 8 + rq;
                unsigned b0 = Ks[nn * STR + kb];
                unsigned b1 = Ks[nn * STR + kb + 4];
                mma8(s[ni], a0, a1, a2, a3, b0, b1);
            }
        }

        // mask text region
        if (kvb < LTXT) {
#pragma unroll
            for (int ni = 0; ni < 8; ni++) {
                int col0 = kvb + wn + ni * 8 + 2 * (lane & 3);
                if (col0 >= len)     { s[ni][0] = -INFINITY; s[ni][2] = -INFINITY; }
                if (col0 + 1 >= len) { s[ni][1] = -INFINITY; s[ni][3] = -INFINITY; }
            }
        }

        // row max (partial over this warp's 64 cols)
        float pm0 = -INFINITY, pm1 = -INFINITY;
#pragma unroll
        for (int ni = 0; ni < 8; ni++) {
            pm0 = fmaxf(pm0, fmaxf(s[ni][0], s[ni][1]));
            pm1 = fmaxf(pm1, fmaxf(s[ni][2], s[ni][3]));
        }
        pm0 = fmaxf(pm0, __shfl_xor_sync(0xffffffffu, pm0, 1));
        pm0 = fmaxf(pm0, __shfl_xor_sync(0xffffffffu, pm0, 2));
        pm1 = fmaxf(pm1, __shfl_xor_sync(0xffffffffu, pm1, 1));
        pm1 = fmaxf(pm1, __shfl_xor_sync(0xffffffffu, pm1, 2));
        if ((lane & 3) == 0) {
            redm[(wm + rq) * 2 + wnid]     = pm0;
            redm[(wm + 8 + rq) * 2 + wnid] = pm1;
        }
        __syncthreads();
        float tm0 = fmaxf(redm[(wm + rq) * 2],     redm[(wm + rq) * 2 + 1]);
        float tm1 = fmaxf(redm[(wm + 8 + rq) * 2], redm[(wm + 8 + rq) * 2 + 1]);
        float mn0 = fmaxf(m0r, tm0);
        float mn1 = fmaxf(m1r, tm1);
        float al0 = __expf(m0r - mn0);
        float al1 = __expf(m1r - mn1);
        m0r = mn0; m1r = mn1;

        // p = exp(s - m), partial row sums, store P to smem (tf32)
        float ps0 = 0.f, ps1 = 0.f;
#pragma unroll
        for (int ni = 0; ni < 8; ni++) {
            float p0 = __expf(s[ni][0] - mn0);
            float p1 = __expf(s[ni][1] - mn0);
            float p2 = __expf(s[ni][2] - mn1);
            float p3 = __expf(s[ni][3] - mn1);
            ps0 += p0 + p1;
            ps1 += p2 + p3;
            int cc = wn + ni * 8 + 2 * (lane & 3);
            unsigned* d0 = &Ps[(wm + rq) * STR + cc];
            d0[0] = f2tf(p0); d0[1] = f2tf(p1);
            unsigned* d1 = &Ps[(wm + 8 + rq) * STR + cc];
            d1[0] = f2tf(p2); d1[1] = f2tf(p3);
        }
        ps0 += __shfl_xor_sync(0xffffffffu, ps0, 1);
        ps0 += __shfl_xor_sync(0xffffffffu, ps0, 2);
        ps1 += __shfl_xor_sync(0xffffffffu, ps1, 1);
        ps1 += __shfl_xor_sync(0xffffffffu, ps1, 2);
        if ((lane & 3) == 0) {
            reds[(wm + rq) * 2 + wnid]     = ps0;
            reds[(wm + 8 + rq) * 2 + wnid] = ps1;
        }

        // rescale O while waiting
#pragma unroll
        for (int ni = 0; ni < 8; ni++) {
            o[ni][0] *= al0; o[ni][1] *= al0;
            o[ni][2] *= al1; o[ni][3] *= al1;
        }
        __syncthreads();
        l0 = l0 * al0 + reds[(wm + rq) * 2]     + reds[(wm + rq) * 2 + 1];
        l1 = l1 * al1 + reds[(wm + 8 + rq) * 2] + reds[(wm + 8 + rq) * 2 + 1];

        // O += P @ V   (contract over 128 kv)
#pragma unroll
        for (int ks = 0; ks < 16; ks++) {
            const int kb = ks * 8 + (lane & 3);
            unsigned a0 = Ps[(wm + rq) * STR + kb];
            unsigned a1 = Ps[(wm + 8 + rq) * STR + kb];
            unsigned a2 = Ps[(wm + rq) * STR + kb + 4];
            unsigned a3 = Ps[(wm + 8 + rq) * STR + kb + 4];
#pragma unroll
            for (int ni = 0; ni < 8; ni++) {
                int dd = wn + ni * 8 + rq;
                unsigned b0 = Vs[kb * STR + dd];
                unsigned b1 = Vs[(kb + 4) * STR + dd];
                mma8(o[ni], a0, a1, a2, a3, b0, b1);
            }
        }
    }

    // epilogue: divide by l, write directly to [B, L, H*DH]
    float inv0 = 1.f / l0, inv1 = 1.f / l1;
    int row0 = q0 + wm + rq;
#pragma unroll
    for (int ni = 0; ni < 8; ni++) {
        int cc = h * DHD + wn + ni * 8 + 2 * (lane & 3);
        *(float2*)&g_attn2[((long)(b * LIMG + row0)) * (NH * DHD) + cc] =
            make_float2(o[ni][0] * inv0, o[ni][1] * inv0);
        *(float2*)&g_attn2[((long)(b * LIMG + row0 + 8)) * (NH * DHD) + cc] =
            make_float2(o[ni][2] * inv1, o[ni][3] * inv1);
    }
}

// ---------------- image QKV transform: RMSNorm + RoPE + layout --------------
__global__ void __launch_bounds__(256) transform_img(
    const float* __restrict__ rope, const float* __restrict__ gq,
    const float* __restrict__ gk)
{
    int r    = blockIdx.x * 8 + (threadIdx.x >> 5);
    int lane = threadIdx.x & 31;
    int h  = r & (NH - 1);
    int bl = r >> 4;
    int l  = bl & (LIMG - 1);
    int b  = bl >> 11;
    int d  = lane * 4;

    const float* row = g_qkv_raw + (long)bl * (3 * DMODEL) + h * DHD;
    float4 q = *(const float4*)&row[d];
    float4 k = *(const float4*)&row[DMODEL + d];
    float4 v = *(const float4*)&row[2 * DMODEL + d];

    float sq = q.x * q.x + q.y * q.y + q.z * q.z + q.w * q.w;
    float sk = k.x * k.x + k.y * k.y + k.z * k.z + k.w * k.w;
#pragma unroll
    for (int o = 16; o; o >>= 1) {
        sq += __shfl_xor_sync(0xffffffffu, sq, o);
        sk += __shfl_xor_sync(0xffffffffu, sk, o);
    }
    float rq = rsqrtf(sq * (1.f / DHD) + EPSV);
    float rk = rsqrtf(sk * (1.f / DHD) + EPSV);

    float4 wq = *(const float4*)&gq[d];
    float4 wk = *(const float4*)&gk[d];
    q.x *= rq * wq.x; q.y *= rq * wq.y; q.z *= rq * wq.z; q.w *= rq * wq.w;
    k.x *= rk * wk.x; k.y *= rk * wk.y; k.z *= rk * wk.z; k.w *= rk * wk.w;

    const float* fc = rope + (((long)bl) * 64 + lane * 2) * 4;
    float4 f0 = *(const float4*)fc;
    float4 f1 = *(const float4*)(fc + 4);

    float4 qo, ko;
    qo.x = f0.x * q.x + f0.y * q.y;  qo.y = f0.z * q.x + f0.w * q.y;
    qo.z = f1.x * q.z + f1.y * q.w;  qo.w = f1.z * q.z + f1.w * q.w;
    ko.x = f0.x * k.x + f0.y * k.y;  ko.y = f0.z * k.x + f0.w * k.y;
    ko.z = f1.x * k.z + f1.y * k.w;  ko.w = f1.z * k.z + f1.w * k.w;

    qo.x *= SCALE; qo.y *= SCALE; qo.z *= SCALE; qo.w *= SCALE;

    long qi = (((long)(b * NH + h)) * LIMG + l) * DHD + d;
    *(float4*)&g_qbuf[qi] = qo;
    long ki = (((long)(b * NH + h)) * LKTOT + (LTXT + l)) * DHD + d;
    *(float4*)&g_kbuf[ki] = ko;
    *(float4*)&g_vbuf[ki] = v;
}

// ---------------- text KV transform: RMSNorm(k) + layout --------------------
__global__ void __launch_bounds__(256) transform_txt(const float* __restrict__ gak)
{
    int r    = blockIdx.x * 8 + (threadIdx.x >> 5);
    int lane = threadIdx.x & 31;
    int h  = r & (NH - 1);
    int bl = r >> 4;
    int l  = bl & (LTXT - 1);
    int b  = bl >> 9;
    int d  = lane * 4;

    const float* row = g_kv_raw + (long)bl * (2 * DMODEL) + h * DHD;
    float4 k = *(const float4*)&row[d];
    float4 v = *(const float4*)&row[DMODEL + d];

    float sk = k.x * k.x + k.y * k.y + k.z * k.z + k.w * k.w;
#pragma unroll
    for (int o = 16; o; o >>= 1) sk += __shfl_xor_sync(0xffffffffu, sk, o);
    float rk = rsqrtf(sk * (1.f / DHD) + EPSV);

    float4 wk = *(const float4*)&gak[d];
    k.x *= rk * wk.x; k.y *= rk * wk.y; k.z *= rk * wk.z; k.w *= rk * wk.w;

    long ki = (((long)(b * NH + h)) * LKTOT + l) * DHD + d;
    *(float4*)&g_kbuf[ki] = k;
    *(float4*)&g_vbuf[ki] = v;
}

// ---------------- mask lengths (dtype-agnostic: bool(1B) or int32) ----------
__global__ void lengths_kernel(const unsigned char* __restrict__ mask)
{
    __shared__ int red[256];
    int b = blockIdx.x;
    int es = (mask[1] != 0) ? 1 : 4;
    int nbytes = LTXT * es;
    const unsigned char* p = mask + (long)b * nbytes;
    int c = 0;
    for (int i = threadIdx.x; i < nbytes; i += 256) c += (p[i] != 0);
    red[threadIdx.x] = c;
    __syncthreads();
    for (int o = 128; o; o >>= 1) {
        if (threadIdx.x < o) red[threadIdx.x] += red[threadIdx.x + o];
        __syncthreads();
    }
    if (threadIdx.x == 0) g_len[b] = red[0];
}

// ---------------- launch ----------------------------------------------------
extern "C" void kernel_launch(void* const* d_in, const int* in_sizes, int n_in,
                              void* d_out, int out_size)
{
    const float* hidden = (const float*)d_in[0];
    const float* enc    = (const float*)d_in[1];
    const unsigned char* mask = (const unsigned char*)d_in[2];
    const float* rope   = (const float*)d_in[3];
    const float* w_qkv  = (const float*)d_in[4];
    const float* w_kv   = (const float*)d_in[5];
    const float* w_o    = (const float*)d_in[6];
    const float* gq     = (const float*)d_in[7];
    const float* gk     = (const float*)d_in[8];
    const float* gak    = (const float*)d_in[9];
    float* out = (float*)d_out;

    float *qkv_raw, *kv_raw, *attn2;
    cudaGetSymbolAddress((void**)&qkv_raw, g_qkv_raw);
    cudaGetSymbolAddress((void**)&kv_raw,  g_kv_raw);
    cudaGetSymbolAddress((void**)&attn2,   g_attn2);

    static int smem_set = 0;
    if (!smem_set) {
        cudaFuncSetAttribute(flash_kernel,
                             cudaFuncAttributeMaxDynamicSharedMemorySize,
                             FLASH_SMEM);
        smem_set = 1;
    }

    dim3 blk(256);

    // 1) image QKV projection: [4096,2048]@[2048,6144]
    gemm_tf32<<<dim3(6144 / 128, 4096 / 128, 1), blk>>>(
        hidden, w_qkv, qkv_raw, 4096, 6144, 2048);
    // 2) text KV projection: [1024,2048]@[2048,4096]
    gemm_tf32<<<dim3(4096 / 128, 1024 / 128, 1), blk>>>(
        enc, w_kv, kv_raw, 1024, 4096, 2048);
    // 3) transforms + mask lengths
    transform_img<<<BB * LIMG * NH / 8, blk>>>(rope, gq, gk);
    transform_txt<<<BB * LTXT * NH / 8, blk>>>(gak);
    lengths_kernel<<<BB, blk>>>(mask);
    // 4) fused flash attention -> g_attn2 in [B, L, H*DH]
    flash_kernel<<<dim3(LIMG / QT, BB * NH), blk, FLASH_SMEM>>>();
    // 5) output projection: [4096,2048]@[2048,2048]
    gemm_tf32<<<dim3(2048 / 128, 4096 / 128, 1), blk>>>(
        attn2, w_o, out, 4096, 2048, 2048);
}